// round 11
// baseline (speedup 1.0000x reference)
#include <cuda_runtime.h>
#include <cuda_fp16.h>

#define NN 50000
#define DD 128
#define EE 800000

// Scratch (allocation-free rule: __device__ globals)
__device__ __half2 g_fjh[NN * 64];   // fj rows in fp16, 64 half2 (=128 cols) per row
__device__ float   g_a1[NN];
__device__ float   g_a2[NN];

__device__ __forceinline__ unsigned long long pack2(float a) {
    unsigned long long r;
    asm("mov.b64 %0, {%1, %1};" : "=l"(r) : "f"(a));
    return r;
}
__device__ __forceinline__ void unpack2(unsigned long long v, float& lo, float& hi) {
    asm("mov.b64 {%0, %1}, %2;" : "=f"(lo), "=f"(hi) : "l"(v));
}
__device__ __forceinline__ unsigned long long ffma2(unsigned long long a,
                                                    unsigned long long b,
                                                    unsigned long long c) {
    unsigned long long d;
    asm("fma.rn.f32x2 %0, %1, %2, %3;" : "=l"(d) : "l"(a), "l"(b), "l"(c));
    return d;
}

// ---------------------------------------------------------------------------
// Kernel 1: fused dense part (proven f32x2 GEMM, at the fp32 roofline).
//   fi = relu(X W1^T + b1), fj = relu(X W2^T + b2)
//   a1 = fi.wa1 + ba1,      a2 = fj.wa2 + ba2
//   out = fi + sigmoid(a1 + a2) * fj   (self-loop folded, fp32)
//   fj stashed as fp16 (half2) for the edge kernel's gather.
// ---------------------------------------------------------------------------
__global__ __launch_bounds__(512, 1) void gat_gemm(
    const float* __restrict__ X,
    const float* __restrict__ W1, const float* __restrict__ b1,
    const float* __restrict__ W2, const float* __restrict__ b2,
    const float* __restrict__ wa1, const float* __restrict__ ba1,
    const float* __restrict__ wa2, const float* __restrict__ ba2,
    float* __restrict__ out)
{
    extern __shared__ float smem[];
    float* sA = smem;              // [128][128]
    float* sB = smem + 128 * 128;  // [128][256] : sB[k][j] = W[j][k]

    const int tid = threadIdx.x;
    const int block_row = blockIdx.x * 128;

    for (int i = tid; i < 128 * 32; i += 512) {
        int row = i >> 5, c4 = i & 31;
        float4 v = make_float4(0.f, 0.f, 0.f, 0.f);
        int grow = block_row + row;
        if (grow < NN) v = ((const float4*)X)[grow * 32 + c4];
        ((float4*)sA)[row * 32 + c4] = v;
    }
    for (int i = tid; i < 128 * 32; i += 512) {
        int j = i & 127;
        int k = (i >> 7) << 2;
        float4 v = ((const float4*)W1)[(j * 128 + k) >> 2];
        sB[(k + 0) * 256 + j] = v.x;
        sB[(k + 1) * 256 + j] = v.y;
        sB[(k + 2) * 256 + j] = v.z;
        sB[(k + 3) * 256 + j] = v.w;
        float4 w = ((const float4*)W2)[(j * 128 + k) >> 2];
        sB[(k + 0) * 256 + 128 + j] = w.x;
        sB[(k + 1) * 256 + 128 + j] = w.y;
        sB[(k + 2) * 256 + 128 + j] = w.z;
        sB[(k + 3) * 256 + 128 + j] = w.w;
    }
    __syncthreads();

    const int tx = tid & 31;
    const int ty = tid >> 5;

    unsigned long long acc[8][4];
    #pragma unroll
    for (int r = 0; r < 8; r++)
        #pragma unroll
        for (int p = 0; p < 4; p++) acc[r][p] = 0ull;

    const float* aBase = sA + (ty * 8) * 128;
    const float* bBase = sB + 2 * tx;

    #pragma unroll 2
    for (int k = 0; k < 128; k += 2) {
        unsigned long long bq0[4], bq1[4];
        #pragma unroll
        for (int p = 0; p < 4; p++) {
            bq0[p] = *(const unsigned long long*)(bBase + (k + 0) * 256 + p * 64);
            bq1[p] = *(const unsigned long long*)(bBase + (k + 1) * 256 + p * 64);
        }
        #pragma unroll
        for (int r = 0; r < 8; r++) {
            float2 av = *(const float2*)(aBase + r * 128 + k);
            unsigned long long a0 = pack2(av.x);
            unsigned long long a1p = pack2(av.y);
            #pragma unroll
            for (int p = 0; p < 4; p++) {
                acc[r][p] = ffma2(a0, bq0[p], acc[r][p]);
                acc[r][p] = ffma2(a1p, bq1[p], acc[r][p]);
            }
        }
    }

    const float vba1 = *ba1;
    const float vba2 = *ba2;
    float wv1[4], wv2[4], bv1[4], bv2[4];
    {
        int c0 = 2 * tx, c1 = 2 * tx + 1, c2 = 64 + 2 * tx, c3 = 65 + 2 * tx;
        wv1[0] = wa1[c0]; wv1[1] = wa1[c1]; wv1[2] = wa1[c2]; wv1[3] = wa1[c3];
        wv2[0] = wa2[c0]; wv2[1] = wa2[c1]; wv2[2] = wa2[c2]; wv2[3] = wa2[c3];
        bv1[0] = b1[c0];  bv1[1] = b1[c1];  bv1[2] = b1[c2];  bv1[3] = b1[c3];
        bv2[0] = b2[c0];  bv2[1] = b2[c1];  bv2[2] = b2[c2];  bv2[3] = b2[c3];
    }

    #pragma unroll
    for (int r = 0; r < 8; r++) {
        int grow = block_row + ty * 8 + r;
        if (grow >= NN) continue;
        float fi[4], fj[4];
        unpack2(acc[r][0], fi[0], fi[1]);
        unpack2(acc[r][1], fi[2], fi[3]);
        unpack2(acc[r][2], fj[0], fj[1]);
        unpack2(acc[r][3], fj[2], fj[3]);
        float pa1 = 0.f, pa2 = 0.f;
        #pragma unroll
        for (int i = 0; i < 4; i++) {
            fi[i] = fmaxf(fi[i] + bv1[i], 0.f);
            fj[i] = fmaxf(fj[i] + bv2[i], 0.f);
            pa1 += fi[i] * wv1[i];
            pa2 += fj[i] * wv2[i];
        }
        #pragma unroll
        for (int off = 16; off > 0; off >>= 1) {
            pa1 += __shfl_xor_sync(0xffffffffu, pa1, off);
            pa2 += __shfl_xor_sync(0xffffffffu, pa2, off);
        }
        float A1 = pa1 + vba1;
        float A2 = pa2 + vba2;
        if (tx == 0) { g_a1[grow] = A1; g_a2[grow] = A2; }
        float att = 1.0f / (1.0f + __expf(-(A1 + A2)));

        float* orow = out + (size_t)grow * DD;
        *(float2*)(orow + 2 * tx)      = make_float2(fi[0] + att * fj[0],
                                                     fi[1] + att * fj[1]);
        *(float2*)(orow + 64 + 2 * tx) = make_float2(fi[2] + att * fj[2],
                                                     fi[3] + att * fj[3]);
        __half2* frow = g_fjh + (size_t)grow * 64;
        frow[tx]      = __floats2half2_rn(fj[0], fj[1]);
        frow[32 + tx] = __floats2half2_rn(fj[2], fj[3]);
    }
}

// ---------------------------------------------------------------------------
// Kernel 2: block-staged edge scatter.
//   Stage 1: 64 edges/block resolved in parallel (r, c, att) -> smem.
//   Stage 2: 8 warps x 8 edges; all gathers issued before the REDGs (MLP~8).
// ---------------------------------------------------------------------------
__global__ __launch_bounds__(256) void gat_edge(const int* __restrict__ ei,
                                                float* __restrict__ out)
{
    __shared__ int   sR[64];
    __shared__ int   sC[64];
    __shared__ float sAtt[64];

    const int tid = threadIdx.x;
    const int eb = blockIdx.x * 64;

    if (tid < 64) {
        const int r = __ldg(ei + eb + tid);
        const int c = __ldg(ei + EE + eb + tid);
        const float s = g_a1[r] + g_a2[c];
        sR[tid] = r;
        sC[tid] = c;
        sAtt[tid] = 1.0f / (1.0f + __expf(-s));
    }
    __syncthreads();

    const int warp = tid >> 5;
    const int lane = tid & 31;
    const int e0 = warp * 8;

    // Read edge descriptors from smem (fast, uniform per warp)
    int   r[8], c[8];
    float att[8];
    #pragma unroll
    for (int j = 0; j < 8; j++) {
        r[j]   = sR[e0 + j];
        c[j]   = sC[e0 + j];
        att[j] = sAtt[e0 + j];
    }

    // Issue all 8 gathers back-to-back (8 independent LDG.64 in flight)
    uint2 u[8];
    #pragma unroll
    for (int j = 0; j < 8; j++)
        u[j] = *(const uint2*)(g_fjh + (size_t)c[j] * 64 + lane * 2);

    // Fire the 8 REDGs (no return dependency)
    #pragma unroll
    for (int j = 0; j < 8; j++) {
        const float2 fa = __half22float2(*(const __half2*)&u[j].x);
        const float2 fb = __half22float2(*(const __half2*)&u[j].y);
        float* p = out + (size_t)r[j] * DD + lane * 4;
        asm volatile("red.global.add.v4.f32 [%0], {%1, %2, %3, %4};"
                     :: "l"(p), "f"(att[j] * fa.x), "f"(att[j] * fa.y),
                        "f"(att[j] * fb.x), "f"(att[j] * fb.y)
                     : "memory");
    }
}

// ---------------------------------------------------------------------------

extern "C" void kernel_launch(void* const* d_in, const int* in_sizes, int n_in,
                              void* d_out, int out_size)
{
    const float* X   = (const float*)d_in[0];
    const float* W1  = (const float*)d_in[1];
    const float* b1  = (const float*)d_in[2];
    const float* W2  = (const float*)d_in[3];
    const float* b2  = (const float*)d_in[4];
    const float* wa1 = (const float*)d_in[5];
    const float* ba1 = (const float*)d_in[6];
    const float* wa2 = (const float*)d_in[7];
    const float* ba2 = (const float*)d_in[8];
    const int*   ei  = (const int*)d_in[9];
    float* out = (float*)d_out;

    const int smem = (128 * 128 + 128 * 256) * 4;  // 192KB
    cudaFuncSetAttribute(gat_gemm, cudaFuncAttributeMaxDynamicSharedMemorySize, smem);

    gat_gemm<<<(NN + 127) / 128, 512, smem>>>(X, W1, b1, W2, b2,
                                              wa1, ba1, wa2, ba2, out);
    gat_edge<<<EE / 64, 256>>>(ei, out);   // 12500 blocks x 64 edges
}

// round 13
// speedup vs baseline: 2.0078x; 2.0078x over previous
#include <cuda_runtime.h>
#include <cuda_fp16.h>
#include <cstdint>

#define NN 50000
#define DD 128
#define EE 800000

// Scratch (allocation-free rule: __device__ globals)
__device__ __half2 g_fjh[NN * 64];   // fj rows in fp16, 64 half2 (=128 cols) per row
__device__ float   g_a1[NN];
__device__ float   g_a2[NN];

// ---------------------------------------------------------------------------
// m16n8k16 fp16 mma, fp32 accumulate (sm_80+ baseline PTX; HMMA on sm_103).
// Fragments (g=lane/4, t=lane%4), k-extension of verified R4 m16n8k8 layout:
//   A a0=(g,2t..2t+1) a1=(g+8,2t..) a2=(g,2t+8..) a3=(g+8,2t+8..)   [half2/reg]
//   B b0=(k 2t..2t+1, n g) b1=(k 2t+8..2t+9, n g)                   [half2/reg]
//   C c0=(g,2t) c1=(g,2t+1) c2=(g+8,2t) c3=(g+8,2t+1)               [fp32]
// ---------------------------------------------------------------------------
__device__ __forceinline__ void mma_f16(float* c, const uint32_t* a,
                                        uint32_t b0, uint32_t b1) {
    asm volatile(
        "mma.sync.aligned.m16n8k16.row.col.f32.f16.f16.f32 "
        "{%0,%1,%2,%3}, {%4,%5,%6,%7}, {%8,%9}, {%0,%1,%2,%3};"
        : "+f"(c[0]), "+f"(c[1]), "+f"(c[2]), "+f"(c[3])
        : "r"(a[0]), "r"(a[1]), "r"(a[2]), "r"(a[3]), "r"(b0), "r"(b1));
}

// SMEM layout.
// Phase 1 (mainloop), as uint32 (=half2) units:
//   sAu [128][68]  (rows of X tile, 64 half2 + 4 pad)        u32 idx 0..8703
//   sBu [256][68]  (rows n of [W1;W2], k as half2)           u32 idx 8704..26111
// Phase 2 (epilogue), as float units, overlaying phase 1 (dead by then):
//   EP  [128][264] fp32                                      float idx 0..33791
// Persistent (after EP region), float units:
//   par  b1|b2|wa1|wa2 at 33792..34303
//   sA1  34304..34431,  sA2  34432..34559
#define SBU_OFF   8704
#define EPS       264
#define OFF_PAR_F 33792
#define OFF_A1_F  34304
#define OFF_A2_F  34432
#define SM_BYTES  (34560 * 4)   // 138240

// ---------------------------------------------------------------------------
// Kernel 1: fp16 tensor-core GEMM + fused GAT epilogue.
//   D[128x256] = X_tile[128x128] @ [W1;W2]^T  (fp16 in, fp32 accum)
//   fi = relu(D[:, :128]+b1), fj = relu(D[:,128:]+b2)
//   a1 = fi.wa1+ba1, a2 = fj.wa2+ba2
//   out = fi + sigmoid(a1+a2)*fj (self-loop); stash fj (fp16), a1, a2.
// 512 threads / 16 warps; warp tile 32 rows x 64 cols; 8 k-steps of K=16.
// ---------------------------------------------------------------------------
__global__ __launch_bounds__(512, 1) void gat_gemm(
    const float* __restrict__ X,
    const float* __restrict__ W1, const float* __restrict__ b1,
    const float* __restrict__ W2, const float* __restrict__ b2,
    const float* __restrict__ wa1, const float* __restrict__ ba1,
    const float* __restrict__ wa2, const float* __restrict__ ba2,
    float* __restrict__ out)
{
    extern __shared__ float sm[];
    uint32_t* sAu = (uint32_t*)sm;
    uint32_t* sBu = sAu + SBU_OFF;
    float* par = sm + OFF_PAR_F;
    float* sA1 = sm + OFF_A1_F;
    float* sA2 = sm + OFF_A2_F;

    const int tid  = threadIdx.x;
    const int warp = tid >> 5;
    const int lane = tid & 31;
    const int g    = lane >> 2;
    const int t    = lane & 3;
    const int block_row = blockIdx.x * 128;

    if (tid < 128) {
        par[tid]       = b1[tid];
        par[128 + tid] = b2[tid];
        par[256 + tid] = wa1[tid];
        par[384 + tid] = wa2[tid];
        sA1[tid] = 0.f;
        sA2[tid] = 0.f;
    }

    // Stage A (X tile) as half2
    for (int i = tid; i < 128 * 32; i += 512) {
        int r = i >> 5, c4 = i & 31;
        float4 v = make_float4(0.f, 0.f, 0.f, 0.f);
        if (block_row + r < NN) v = ((const float4*)X)[(block_row + r) * 32 + c4];
        __half2 h0 = __floats2half2_rn(v.x, v.y);
        __half2 h1 = __floats2half2_rn(v.z, v.w);
        sAu[r * 68 + c4 * 2]     = *(uint32_t*)&h0;
        sAu[r * 68 + c4 * 2 + 1] = *(uint32_t*)&h1;
    }
    // Stage B ([W1;W2], rows n, k contiguous) as half2
    for (int i = tid; i < 256 * 32; i += 512) {
        int n = i >> 5, c4 = i & 31;
        float4 v = (n < 128) ? ((const float4*)W1)[n * 32 + c4]
                             : ((const float4*)W2)[(n - 128) * 32 + c4];
        __half2 h0 = __floats2half2_rn(v.x, v.y);
        __half2 h1 = __floats2half2_rn(v.z, v.w);
        sBu[n * 68 + c4 * 2]     = *(uint32_t*)&h0;
        sBu[n * 68 + c4 * 2 + 1] = *(uint32_t*)&h1;
    }
    __syncthreads();

    const int wr = warp & 3;    // row group (x32 rows)
    const int wc = warp >> 2;   // col group (x64 cols)

    float c[2][8][4];
    #pragma unroll
    for (int rt = 0; rt < 2; rt++)
        #pragma unroll
        for (int ct = 0; ct < 8; ct++)
            #pragma unroll
            for (int i = 0; i < 4; i++) c[rt][ct][i] = 0.f;

    #pragma unroll
    for (int ks = 0; ks < 8; ks++) {
        const int kp = ks * 8 + t;           // half2 column within the row
        uint32_t a[2][4];
        #pragma unroll
        for (int rt = 0; rt < 2; rt++) {
            const uint32_t* ap = sAu + (wr * 32 + rt * 16 + g) * 68;
            a[rt][0] = ap[kp];
            a[rt][1] = ap[8 * 68 + kp];
            a[rt][2] = ap[kp + 4];
            a[rt][3] = ap[8 * 68 + kp + 4];
        }
        #pragma unroll
        for (int ct = 0; ct < 8; ct++) {
            const uint32_t* bp = sBu + (wc * 64 + ct * 8 + g) * 68;
            uint32_t b0 = bp[kp];
            uint32_t b1r = bp[kp + 4];
            mma_f16(c[0][ct], a[0], b0, b1r);
            mma_f16(c[1][ct], a[1], b0, b1r);
        }
    }
    __syncthreads();   // sA/sB dead; EP overlays them

    // Bias + ReLU in regs; partial a-dots; write fi/fj to exchange buffer.
    float* EP = sm;    // [128][264]; cols 0..127 = fi, 128..255 = fj
    const int colbase = wc * 64;
    float pa[2][2] = {{0.f, 0.f}, {0.f, 0.f}};   // [rt][row half]

    #pragma unroll
    for (int ct = 0; ct < 8; ct++) {
        const int col = colbase + ct * 8 + 2 * t;   // global col (0..255)
        const float w0 = par[256 + col], w1 = par[257 + col];
        const float bb0 = par[col], bb1 = par[col + 1];
        #pragma unroll
        for (int rt = 0; rt < 2; rt++) {
            float f0 = fmaxf(c[rt][ct][0] + bb0, 0.f);
            float f1 = fmaxf(c[rt][ct][1] + bb1, 0.f);
            float f2 = fmaxf(c[rt][ct][2] + bb0, 0.f);
            float f3 = fmaxf(c[rt][ct][3] + bb1, 0.f);
            pa[rt][0] += f0 * w0 + f1 * w1;
            pa[rt][1] += f2 * w0 + f3 * w1;
            int r0 = wr * 32 + rt * 16 + g;
            *(float2*)(EP + r0 * EPS + col)       = make_float2(f0, f1);
            *(float2*)(EP + (r0 + 8) * EPS + col) = make_float2(f2, f3);
        }
    }
    #pragma unroll
    for (int off = 1; off <= 2; off <<= 1) {
        pa[0][0] += __shfl_xor_sync(0xffffffffu, pa[0][0], off);
        pa[0][1] += __shfl_xor_sync(0xffffffffu, pa[0][1], off);
        pa[1][0] += __shfl_xor_sync(0xffffffffu, pa[1][0], off);
        pa[1][1] += __shfl_xor_sync(0xffffffffu, pa[1][1], off);
    }
    if (t == 0) {
        float* dst = (wc < 2) ? sA1 : sA2;   // wc 0,1 -> fi cols; 2,3 -> fj cols
        atomicAdd(dst + wr * 32 + g,      pa[0][0]);
        atomicAdd(dst + wr * 32 + g + 8,  pa[0][1]);
        atomicAdd(dst + wr * 32 + g + 16, pa[1][0]);
        atomicAdd(dst + wr * 32 + g + 24, pa[1][1]);
    }
    __syncthreads();

    // Final combine: 4 threads per row, 32 cols each.
    {
        const int r = tid >> 2;
        const int grow = block_row + r;
        if (grow < NN) {
            const float A1 = sA1[r] + __ldg(ba1);
            const float A2 = sA2[r] + __ldg(ba2);
            const float att = 1.0f / (1.0f + __expf(-(A1 + A2)));
            if ((tid & 3) == 0) { g_a1[grow] = A1; g_a2[grow] = A2; }
            const int c0 = (tid & 3) * 32;
            float* orow = out + (size_t)grow * DD;
            __half2* frow = g_fjh + (size_t)grow * 64 + (c0 >> 1);
            const float* fi = EP + r * EPS + c0;
            const float* fj = EP + r * EPS + 128 + c0;
            #pragma unroll
            for (int q = 0; q < 8; q++) {
                float4 vi = *(const float4*)(fi + 4 * q);
                float4 vj = *(const float4*)(fj + 4 * q);
                frow[2 * q]     = __floats2half2_rn(vj.x, vj.y);
                frow[2 * q + 1] = __floats2half2_rn(vj.z, vj.w);
                *(float4*)(orow + c0 + 4 * q) =
                    make_float4(vi.x + att * vj.x, vi.y + att * vj.y,
                                vi.z + att * vj.z, vi.w + att * vj.w);
            }
        }
    }
}

// ---------------------------------------------------------------------------
// Kernel 2: edge scatter (R10-proven), 2 edges/warp, fp16 gather,
// fp32 red.global.add.v4.
// ---------------------------------------------------------------------------
__global__ __launch_bounds__(256) void gat_edge(const int* __restrict__ ei,
                                                float* __restrict__ out)
{
    const int warp = threadIdx.x >> 5;
    const int lane = threadIdx.x & 31;
    const int e0 = (blockIdx.x * 8 + warp) * 2;

    const int r0 = __ldg(ei + e0);
    const int r1 = __ldg(ei + e0 + 1);
    const int c0 = __ldg(ei + EE + e0);
    const int c1 = __ldg(ei + EE + e0 + 1);

    const float s0 = g_a1[r0] + g_a2[c0];
    const float s1 = g_a1[r1] + g_a2[c1];

    const uint2 u0 = *(const uint2*)(g_fjh + (size_t)c0 * 64 + lane * 2);
    const uint2 u1 = *(const uint2*)(g_fjh + (size_t)c1 * 64 + lane * 2);

    const float att0 = 1.0f / (1.0f + __expf(-s0));
    const float att1 = 1.0f / (1.0f + __expf(-s1));

    const float2 f0a = __half22float2(*(const __half2*)&u0.x);
    const float2 f0b = __half22float2(*(const __half2*)&u0.y);
    const float2 f1a = __half22float2(*(const __half2*)&u1.x);
    const float2 f1b = __half22float2(*(const __half2*)&u1.y);

    float* p0 = out + (size_t)r0 * DD + lane * 4;
    asm volatile("red.global.add.v4.f32 [%0], {%1, %2, %3, %4};"
                 :: "l"(p0), "f"(att0 * f0a.x), "f"(att0 * f0a.y),
                    "f"(att0 * f0b.x), "f"(att0 * f0b.y)
                 : "memory");
    float* p1 = out + (size_t)r1 * DD + lane * 4;
    asm volatile("red.global.add.v4.f32 [%0], {%1, %2, %3, %4};"
                 :: "l"(p1), "f"(att1 * f1a.x), "f"(att1 * f1a.y),
                    "f"(att1 * f1b.x), "f"(att1 * f1b.y)
                 : "memory");
}

// ---------------------------------------------------------------------------

extern "C" void kernel_launch(void* const* d_in, const int* in_sizes, int n_in,
                              void* d_out, int out_size)
{
    const float* X   = (const float*)d_in[0];
    const float* W1  = (const float*)d_in[1];
    const float* b1  = (const float*)d_in[2];
    const float* W2  = (const float*)d_in[3];
    const float* b2  = (const float*)d_in[4];
    const float* wa1 = (const float*)d_in[5];
    const float* ba1 = (const float*)d_in[6];
    const float* wa2 = (const float*)d_in[7];
    const float* ba2 = (const float*)d_in[8];
    const int*   ei  = (const int*)d_in[9];
    float* out = (float*)d_out;

    cudaFuncSetAttribute(gat_gemm, cudaFuncAttributeMaxDynamicSharedMemorySize,
                         SM_BYTES);

    gat_gemm<<<(NN + 127) / 128, 512, SM_BYTES>>>(X, W1, b1, W2, b2,
                                                  wa1, ba1, wa2, ba2, out);
    gat_edge<<<EE / 16, 256>>>(ei, out);   // 50000 blocks x 8 warps x 2 edges
}

// round 14
// speedup vs baseline: 2.1064x; 1.0491x over previous
#include <cuda_runtime.h>
#include <cuda_fp16.h>
#include <cstdint>

#define NN 50000
#define DD 128
#define EE 800000

// Scratch (allocation-free rule: __device__ globals)
__device__ __half2 g_fjh[NN * 64];   // fj rows in fp16, 64 half2 (=128 cols) per row
__device__ float   g_a1[NN];
__device__ float   g_a2[NN];

// ---------------------------------------------------------------------------
// m16n8k16 fp16 mma, fp32 accumulate (verified R13 fragment layout).
// ---------------------------------------------------------------------------
__device__ __forceinline__ void mma_f16(float* c, const uint32_t* a,
                                        uint32_t b0, uint32_t b1) {
    asm volatile(
        "mma.sync.aligned.m16n8k16.row.col.f32.f16.f16.f32 "
        "{%0,%1,%2,%3}, {%4,%5,%6,%7}, {%8,%9}, {%0,%1,%2,%3};"
        : "+f"(c[0]), "+f"(c[1]), "+f"(c[2]), "+f"(c[3])
        : "r"(a[0]), "r"(a[1]), "r"(a[2]), "r"(a[3]), "r"(b0), "r"(b1));
}

// SMEM layout (64-row tile -> 2 CTAs resident per SM).
// Phase 1 (u32 = half2 units):
//   sAu [64][68]    u32 idx 0..4351
//   sBu [256][68]   u32 idx 4352..21759
// Phase 2 (floats, overlays phase 1):
//   EP  [64][264]   float idx 0..16895
// Persistent (floats, after phase-1 region):
//   par  21760..22271 (b1|b2|wa1|wa2)
//   sA1  22272..22335,  sA2  22336..22399
#define SBU_OFF   4352
#define EPS       264
#define OFF_PAR_F 21760
#define OFF_A1_F  22272
#define OFF_A2_F  22336
#define SM_BYTES  (22400 * 4)   // 89600 -> 2 CTAs/SM (179.2KB)

// ---------------------------------------------------------------------------
// Kernel 1: fp16 tensor-core GEMM + fused GAT epilogue, 64-row tiles.
//   D[64x256] = X_tile[64x128] @ [W1;W2]^T  (fp16 in, fp32 accum)
//   fi = relu(D[:, :128]+b1), fj = relu(D[:,128:]+b2)
//   a1 = fi.wa1+ba1, a2 = fj.wa2+ba2
//   out = fi + sigmoid(a1+a2)*fj (self-loop); stash fj (fp16), a1, a2.
// 256 threads / 8 warps; warp tile 32 rows x 64 cols; 8 k-steps of K=16.
// ---------------------------------------------------------------------------
__global__ __launch_bounds__(256, 2) void gat_gemm(
    const float* __restrict__ X,
    const float* __restrict__ W1, const float* __restrict__ b1,
    const float* __restrict__ W2, const float* __restrict__ b2,
    const float* __restrict__ wa1, const float* __restrict__ ba1,
    const float* __restrict__ wa2, const float* __restrict__ ba2,
    float* __restrict__ out)
{
    extern __shared__ float sm[];
    uint32_t* sAu = (uint32_t*)sm;
    uint32_t* sBu = sAu + SBU_OFF;
    float* par = sm + OFF_PAR_F;
    float* sA1 = sm + OFF_A1_F;
    float* sA2 = sm + OFF_A2_F;

    const int tid  = threadIdx.x;
    const int warp = tid >> 5;
    const int lane = tid & 31;
    const int g    = lane >> 2;
    const int t    = lane & 3;
    const int block_row = blockIdx.x * 64;

    if (tid < 128) {
        par[tid]       = b1[tid];
        par[128 + tid] = b2[tid];
        par[256 + tid] = wa1[tid];
        par[384 + tid] = wa2[tid];
        if (tid < 64) { sA1[tid] = 0.f; sA2[tid] = 0.f; }
    }

    // Stage A (X tile, 64 rows) as half2
    for (int i = tid; i < 64 * 32; i += 256) {
        int r = i >> 5, c4 = i & 31;
        float4 v = make_float4(0.f, 0.f, 0.f, 0.f);
        if (block_row + r < NN) v = ((const float4*)X)[(block_row + r) * 32 + c4];
        __half2 h0 = __floats2half2_rn(v.x, v.y);
        __half2 h1 = __floats2half2_rn(v.z, v.w);
        sAu[r * 68 + c4 * 2]     = *(uint32_t*)&h0;
        sAu[r * 68 + c4 * 2 + 1] = *(uint32_t*)&h1;
    }
    // Stage B ([W1;W2], rows n, k contiguous) as half2 (L2-resident re-read)
    for (int i = tid; i < 256 * 32; i += 256) {
        int n = i >> 5, c4 = i & 31;
        float4 v = (n < 128) ? ((const float4*)W1)[n * 32 + c4]
                             : ((const float4*)W2)[(n - 128) * 32 + c4];
        __half2 h0 = __floats2half2_rn(v.x, v.y);
        __half2 h1 = __floats2half2_rn(v.z, v.w);
        sBu[n * 68 + c4 * 2]     = *(uint32_t*)&h0;
        sBu[n * 68 + c4 * 2 + 1] = *(uint32_t*)&h1;
    }
    __syncthreads();

    const int wr = warp & 1;    // row group (x32 rows)
    const int wc = warp >> 1;   // col group (x64 cols), 0..3

    float c[2][8][4];
    #pragma unroll
    for (int rt = 0; rt < 2; rt++)
        #pragma unroll
        for (int ct = 0; ct < 8; ct++)
            #pragma unroll
            for (int i = 0; i < 4; i++) c[rt][ct][i] = 0.f;

    #pragma unroll
    for (int ks = 0; ks < 8; ks++) {
        const int kp = ks * 8 + t;           // half2 column within the row
        uint32_t a[2][4];
        #pragma unroll
        for (int rt = 0; rt < 2; rt++) {
            const uint32_t* ap = sAu + (wr * 32 + rt * 16 + g) * 68;
            a[rt][0] = ap[kp];
            a[rt][1] = ap[8 * 68 + kp];
            a[rt][2] = ap[kp + 4];
            a[rt][3] = ap[8 * 68 + kp + 4];
        }
        #pragma unroll
        for (int ct = 0; ct < 8; ct++) {
            const uint32_t* bp = sBu + (wc * 64 + ct * 8 + g) * 68;
            uint32_t b0 = bp[kp];
            uint32_t b1r = bp[kp + 4];
            mma_f16(c[0][ct], a[0], b0, b1r);
            mma_f16(c[1][ct], a[1], b0, b1r);
        }
    }
    __syncthreads();   // sA/sB dead; EP overlays them

    // Bias + ReLU in regs; partial a-dots; write fi/fj to exchange buffer.
    float* EP = sm;    // [64][264]; cols 0..127 = fi, 128..255 = fj
    const int colbase = wc * 64;
    float pa[2][2] = {{0.f, 0.f}, {0.f, 0.f}};   // [rt][row half]

    #pragma unroll
    for (int ct = 0; ct < 8; ct++) {
        const int col = colbase + ct * 8 + 2 * t;   // global col (0..255)
        const float w0 = par[256 + col], w1 = par[257 + col];
        const float bb0 = par[col], bb1 = par[col + 1];
        #pragma unroll
        for (int rt = 0; rt < 2; rt++) {
            float f0 = fmaxf(c[rt][ct][0] + bb0, 0.f);
            float f1 = fmaxf(c[rt][ct][1] + bb1, 0.f);
            float f2 = fmaxf(c[rt][ct][2] + bb0, 0.f);
            float f3 = fmaxf(c[rt][ct][3] + bb1, 0.f);
            pa[rt][0] += f0 * w0 + f1 * w1;
            pa[rt][1] += f2 * w0 + f3 * w1;
            int r0 = wr * 32 + rt * 16 + g;
            *(float2*)(EP + r0 * EPS + col)       = make_float2(f0, f1);
            *(float2*)(EP + (r0 + 8) * EPS + col) = make_float2(f2, f3);
        }
    }
    #pragma unroll
    for (int off = 1; off <= 2; off <<= 1) {
        pa[0][0] += __shfl_xor_sync(0xffffffffu, pa[0][0], off);
        pa[0][1] += __shfl_xor_sync(0xffffffffu, pa[0][1], off);
        pa[1][0] += __shfl_xor_sync(0xffffffffu, pa[1][0], off);
        pa[1][1] += __shfl_xor_sync(0xffffffffu, pa[1][1], off);
    }
    if (t == 0) {
        float* dst = (wc < 2) ? sA1 : sA2;   // wc 0,1 -> fi cols; 2,3 -> fj cols
        atomicAdd(dst + wr * 32 + g,      pa[0][0]);
        atomicAdd(dst + wr * 32 + g + 8,  pa[0][1]);
        atomicAdd(dst + wr * 32 + g + 16, pa[1][0]);
        atomicAdd(dst + wr * 32 + g + 24, pa[1][1]);
    }
    __syncthreads();

    // Final combine: 4 threads per row, 32 cols each (r = 0..63).
    {
        const int r = tid >> 2;
        const int grow = block_row + r;
        if (grow < NN) {
            const float A1 = sA1[r] + __ldg(ba1);
            const float A2 = sA2[r] + __ldg(ba2);
            const float att = __fdividef(1.0f, 1.0f + __expf(-(A1 + A2)));
            if ((tid & 3) == 0) { g_a1[grow] = A1; g_a2[grow] = A2; }
            const int c0 = (tid & 3) * 32;
            float* orow = out + (size_t)grow * DD;
            __half2* frow = g_fjh + (size_t)grow * 64 + (c0 >> 1);
            const float* fi = EP + r * EPS + c0;
            const float* fj = EP + r * EPS + 128 + c0;
            #pragma unroll
            for (int q = 0; q < 8; q++) {
                float4 vi = *(const float4*)(fi + 4 * q);
                float4 vj = *(const float4*)(fj + 4 * q);
                frow[2 * q]     = __floats2half2_rn(vj.x, vj.y);
                frow[2 * q + 1] = __floats2half2_rn(vj.z, vj.w);
                *(float4*)(orow + c0 + 4 * q) =
                    make_float4(vi.x + att * vj.x, vi.y + att * vj.y,
                                vi.z + att * vj.z, vi.w + att * vj.w);
            }
        }
    }
}

// ---------------------------------------------------------------------------
// Kernel 2: edge scatter (R10/R13-proven), 2 edges/warp, fp16 gather,
// fp32 red.global.add.v4.
// ---------------------------------------------------------------------------
__global__ __launch_bounds__(256) void gat_edge(const int* __restrict__ ei,
                                                float* __restrict__ out)
{
    const int warp = threadIdx.x >> 5;
    const int lane = threadIdx.x & 31;
    const int e0 = (blockIdx.x * 8 + warp) * 2;

    const int r0 = __ldg(ei + e0);
    const int r1 = __ldg(ei + e0 + 1);
    const int c0 = __ldg(ei + EE + e0);
    const int c1 = __ldg(ei + EE + e0 + 1);

    const float s0 = g_a1[r0] + g_a2[c0];
    const float s1 = g_a1[r1] + g_a2[c1];

    const uint2 u0 = *(const uint2*)(g_fjh + (size_t)c0 * 64 + lane * 2);
    const uint2 u1 = *(const uint2*)(g_fjh + (size_t)c1 * 64 + lane * 2);

    const float att0 = __fdividef(1.0f, 1.0f + __expf(-s0));
    const float att1 = __fdividef(1.0f, 1.0f + __expf(-s1));

    const float2 f0a = __half22float2(*(const __half2*)&u0.x);
    const float2 f0b = __half22float2(*(const __half2*)&u0.y);
    const float2 f1a = __half22float2(*(const __half2*)&u1.x);
    const float2 f1b = __half22float2(*(const __half2*)&u1.y);

    float* p0 = out + (size_t)r0 * DD + lane * 4;
    asm volatile("red.global.add.v4.f32 [%0], {%1, %2, %3, %4};"
                 :: "l"(p0), "f"(att0 * f0a.x), "f"(att0 * f0a.y),
                    "f"(att0 * f0b.x), "f"(att0 * f0b.y)
                 : "memory");
    float* p1 = out + (size_t)r1 * DD + lane * 4;
    asm volatile("red.global.add.v4.f32 [%0], {%1, %2, %3, %4};"
                 :: "l"(p1), "f"(att1 * f1a.x), "f"(att1 * f1a.y),
                    "f"(att1 * f1b.x), "f"(att1 * f1b.y)
                 : "memory");
}

// ---------------------------------------------------------------------------

extern "C" void kernel_launch(void* const* d_in, const int* in_sizes, int n_in,
                              void* d_out, int out_size)
{
    const float* X   = (const float*)d_in[0];
    const float* W1  = (const float*)d_in[1];
    const float* b1  = (const float*)d_in[2];
    const float* W2  = (const float*)d_in[3];
    const float* b2  = (const float*)d_in[4];
    const float* wa1 = (const float*)d_in[5];
    const float* ba1 = (const float*)d_in[6];
    const float* wa2 = (const float*)d_in[7];
    const float* ba2 = (const float*)d_in[8];
    const int*   ei  = (const int*)d_in[9];
    float* out = (float*)d_out;

    cudaFuncSetAttribute(gat_gemm, cudaFuncAttributeMaxDynamicSharedMemorySize,
                         SM_BYTES);

    gat_gemm<<<(NN + 63) / 64, 256, SM_BYTES>>>(X, W1, b1, W2, b2,
                                                wa1, ba1, wa2, ba2, out);
    gat_edge<<<EE / 16, 256>>>(ei, out);   // 50000 blocks x 8 warps x 2 edges
}